// round 1
// baseline (speedup 1.0000x reference)
#include <cuda_runtime.h>
#include <cstdint>

// out[k] = x[i][j] where j = compacted even bits of k, i = compacted odd bits.
// Each thread produces 4 consecutive outputs (one float4 store) from a 2x2
// input block (two float2 loads from rows i and i+1 at column j).
//
// Shapes: x is (8, 64, 256, 256) fp32 -> 512 independent 256x256 images,
// 65536 elements each, 33,554,432 elements total -> 8,388,608 threads.

__global__ __launch_bounds__(256) void morton_gather_kernel(
    const float* __restrict__ in, float* __restrict__ out)
{
    // Thread id -> output element base index g = t*4 (fits in 32 bits: < 2^25)
    unsigned t = blockIdx.x * 256u + threadIdx.x;
    unsigned g = t << 2;                 // output flat element index
    unsigned k = g & 0xFFFFu;            // index within one 256x256 image
    unsigned img = g >> 16;              // which (b, c) image

    // Bit-deinterleave k: even bits -> j, odd bits -> i. Bits 0 and 1 of k are
    // zero here (g is a multiple of 4), so j and i are both even.
    unsigned e = k & 0x5555u;
    unsigned o = (k >> 1) & 0x5555u;
    e = (e | (e >> 1)) & 0x3333u;
    e = (e | (e >> 2)) & 0x0F0Fu;
    e = (e | (e >> 4)) & 0x00FFu;
    o = (o | (o >> 1)) & 0x3333u;
    o = (o | (o >> 2)) & 0x0F0Fu;
    o = (o | (o >> 4)) & 0x00FFu;
    unsigned j = e;                      // column (even)
    unsigned i = o;                      // row    (even)

    const float* base = in + ((size_t)img << 16);
    // Two 8-byte loads from adjacent rows; both offsets are 8B-aligned (j even).
    float2 r0 = *reinterpret_cast<const float2*>(base + (i << 8) + j);
    float2 r1 = *reinterpret_cast<const float2*>(base + ((i + 1u) << 8) + j);

    // out[k]   = x[i][j],   out[k+1] = x[i][j+1]
    // out[k+2] = x[i+1][j], out[k+3] = x[i+1][j+1]
    float4 v = make_float4(r0.x, r0.y, r1.x, r1.y);
    *reinterpret_cast<float4*>(out + g) = v;
}

extern "C" void kernel_launch(void* const* d_in, const int* in_sizes, int n_in,
                              void* d_out, int out_size)
{
    const float* in = (const float*)d_in[0];
    float* out = (float*)d_out;
    // total elements = 8*64*256*256 = 33,554,432; 4 per thread
    const unsigned total_threads = 33554432u / 4u;   // 8,388,608
    const unsigned block = 256u;
    const unsigned grid = total_threads / block;     // 32,768
    morton_gather_kernel<<<grid, block>>>(in, out);
}